// round 4
// baseline (speedup 1.0000x reference)
#include <cuda_runtime.h>

// HSE (hard-sigmoid squeeze-excitation) for x[64, 768, 28, 28] fp32.
//   pooled = mean(x, HW); h = relu(pooled@w1^T + b1); s = hardsig(h@w2^T + b2);
//   out = x * s[b,c]
// Three kernels: pool (warp/plane), fused MLP (block/batch), scale (warp/plane,
// reversed plane order to harvest L2 residue of x from the pool pass).

#define BATCH   64
#define CH      768
#define HID     192
#define HW      784
#define PLANES  (BATCH * CH)   // 49152
#define VEC4    (HW / 4)       // 196 float4 per plane

__device__ float g_pooled[PLANES];
__device__ float g_scale[PLANES];

// ---------------------------------------------------------------------------
// Kernel 1: global average pool. One warp per (b,c) plane of 784 floats.
// 6 full float4 rounds + 4-lane tail, shuffle reduction. Pure HBM read.
// ---------------------------------------------------------------------------
__global__ __launch_bounds__(256) void pool_kernel(const float4* __restrict__ x) {
    int w    = (blockIdx.x * blockDim.x + threadIdx.x) >> 5;
    int lane = threadIdx.x & 31;
    if (w >= PLANES) return;

    const float4* p = x + (size_t)w * VEC4;
    float s = 0.0f;
#pragma unroll
    for (int i = 0; i < 6; i++) {
        float4 v = p[lane + 32 * i];
        s += (v.x + v.y) + (v.z + v.w);
    }
    if (lane < 4) {
        float4 v = p[192 + lane];
        s += (v.x + v.y) + (v.z + v.w);
    }
#pragma unroll
    for (int off = 16; off; off >>= 1)
        s += __shfl_xor_sync(0xffffffffu, s, off);
    if (lane == 0) g_pooled[w] = s * (1.0f / 784.0f);
}

// ---------------------------------------------------------------------------
// Kernel 2: fused MLP. One block per batch row, 192 threads.
//   phase 1: thread j computes h[j] = relu(dot(pooled_b, w1[j]) + b1[j])
//   phase 2: each thread computes 4 outputs s[c] = hardsig(dot(h, w2[c]) + b2[c])
// Weights stream from L2 (w1+w2 = 1.18 MB, L2-resident across blocks).
// ---------------------------------------------------------------------------
__global__ __launch_bounds__(HID) void mlp_kernel(const float4* __restrict__ w1,
                                                  const float*  __restrict__ b1,
                                                  const float4* __restrict__ w2,
                                                  const float*  __restrict__ b2) {
    __shared__ __align__(16) float p_s[CH];
    __shared__ __align__(16) float h_s[HID];

    int b = blockIdx.x;
    int t = threadIdx.x;  // 0..191

#pragma unroll
    for (int i = 0; i < 4; i++)
        p_s[t + HID * i] = g_pooled[b * CH + t + HID * i];
    __syncthreads();

    // phase 1: h = relu(w1 @ pooled + b1)
    const float4* pv   = reinterpret_cast<const float4*>(p_s);
    const float4* wrow = w1 + (size_t)t * (CH / 4);
    float acc = 0.0f;
#pragma unroll 4
    for (int k = 0; k < CH / 4; k++) {
        float4 wv = wrow[k];
        float4 p  = pv[k];
        acc += wv.x * p.x + wv.y * p.y + wv.z * p.z + wv.w * p.w;
    }
    h_s[t] = fmaxf(acc + b1[t], 0.0f);
    __syncthreads();

    // phase 2: s = hardsigmoid(w2 @ h + b2)
    const float4* hv = reinterpret_cast<const float4*>(h_s);
#pragma unroll
    for (int i = 0; i < 4; i++) {
        int c = t + HID * i;
        const float4* w2row = w2 + (size_t)c * (HID / 4);
        float a = 0.0f;
#pragma unroll 4
        for (int k = 0; k < HID / 4; k++) {
            float4 wv = w2row[k];
            float4 h  = hv[k];
            a += wv.x * h.x + wv.y * h.y + wv.z * h.z + wv.w * h.w;
        }
        float z = a + b2[c];
        g_scale[b * CH + c] = __saturatef(fmaf(z, 1.0f / 6.0f, 0.5f));
    }
}

// ---------------------------------------------------------------------------
// Kernel 3: out = x * s[plane]. One warp per plane; planes walked in REVERSE
// so the tail of x left in L2 by the pool pass is re-hit before eviction.
// ---------------------------------------------------------------------------
__global__ __launch_bounds__(256) void scale_kernel(const float4* __restrict__ x,
                                                    float4* __restrict__ out) {
    int w    = (blockIdx.x * blockDim.x + threadIdx.x) >> 5;
    int lane = threadIdx.x & 31;
    if (w >= PLANES) return;

    int plane = PLANES - 1 - w;
    float sv = g_scale[plane];

    const float4* p = x   + (size_t)plane * VEC4;
    float4*       o = out + (size_t)plane * VEC4;

    float4 v[6];
#pragma unroll
    for (int i = 0; i < 6; i++) v[i] = p[lane + 32 * i];
    float4 vt;
    bool tail = lane < 4;
    if (tail) vt = p[192 + lane];

#pragma unroll
    for (int i = 0; i < 6; i++) {
        v[i].x *= sv; v[i].y *= sv; v[i].z *= sv; v[i].w *= sv;
        o[lane + 32 * i] = v[i];
    }
    if (tail) {
        vt.x *= sv; vt.y *= sv; vt.z *= sv; vt.w *= sv;
        o[192 + lane] = vt;
    }
}

// ---------------------------------------------------------------------------
extern "C" void kernel_launch(void* const* d_in, const int* in_sizes, int n_in,
                              void* d_out, int out_size) {
    const float4* x  = (const float4*)d_in[0];
    const float4* w1 = (const float4*)d_in[1];
    const float*  b1 = (const float*)d_in[2];
    const float4* w2 = (const float4*)d_in[3];
    const float*  b2 = (const float*)d_in[4];
    float4* out = (float4*)d_out;

    const int warps_per_block = 256 / 32;
    const int grid = (PLANES + warps_per_block - 1) / warps_per_block;  // 6144

    pool_kernel<<<grid, 256>>>(x);
    mlp_kernel<<<BATCH, HID>>>(w1, b1, w2, b2);
    scale_kernel<<<grid, 256>>>(x, out);
}

// round 5
// speedup vs baseline: 1.0478x; 1.0478x over previous
#include <cuda_runtime.h>

// HSE (hard-sigmoid squeeze-excitation) for x[64, 768, 28, 28] fp32.
// R4 changes vs R3 (121.3us):
//  - mlp: 768 threads/block, phase-1 dot split 4-way + shfl combine (latency fix)
//  - scale: __stcs streaming stores so output doesn't evict x's L2 residue;
//    planes still walked in reverse to hit the pool pass's L2 tail.

#define BATCH   64
#define CH      768
#define HID     192
#define HW      784
#define PLANES  (BATCH * CH)   // 49152
#define VEC4    (HW / 4)       // 196 float4 per plane

__device__ float g_pooled[PLANES];
__device__ float g_scale[PLANES];

// ---------------------------------------------------------------------------
// Kernel 1: global average pool. One warp per (b,c) plane of 784 floats.
// 77% DRAM / 6.1 TB/s measured — at the ceiling, unchanged.
// ---------------------------------------------------------------------------
__global__ __launch_bounds__(256) void pool_kernel(const float4* __restrict__ x) {
    int w    = (blockIdx.x * blockDim.x + threadIdx.x) >> 5;
    int lane = threadIdx.x & 31;
    if (w >= PLANES) return;

    const float4* p = x + (size_t)w * VEC4;
    float s = 0.0f;
#pragma unroll
    for (int i = 0; i < 6; i++) {
        float4 v = p[lane + 32 * i];
        s += (v.x + v.y) + (v.z + v.w);
    }
    if (lane < 4) {
        float4 v = p[192 + lane];
        s += (v.x + v.y) + (v.z + v.w);
    }
#pragma unroll
    for (int off = 16; off; off >>= 1)
        s += __shfl_xor_sync(0xffffffffu, s, off);
    if (lane == 0) g_pooled[w] = s * (1.0f / 784.0f);
}

// ---------------------------------------------------------------------------
// Kernel 2: fused MLP. One block per batch row, 768 threads.
//   phase 1: 4 threads per h-output (48 float4 each), shfl_xor combine.
//   phase 2: 1 thread per c-output (48 float4 from smem h + w2 row).
// ---------------------------------------------------------------------------
__global__ __launch_bounds__(CH) void mlp_kernel(const float4* __restrict__ w1,
                                                 const float*  __restrict__ b1,
                                                 const float4* __restrict__ w2,
                                                 const float*  __restrict__ b2) {
    __shared__ __align__(16) float p_s[CH];
    __shared__ __align__(16) float h_s[HID];

    int b = blockIdx.x;
    int t = threadIdx.x;  // 0..767

    p_s[t] = g_pooled[b * CH + t];
    __syncthreads();

    // phase 1: h[j] = relu(dot(w1[j], pooled) + b1[j]); j = t>>2, quarter q = t&3
    {
        int j = t >> 2;
        int q = t & 3;
        const float4* pv   = reinterpret_cast<const float4*>(p_s) + q * 48;
        const float4* wrow = w1 + (size_t)j * (CH / 4) + q * 48;
        float acc = 0.0f;
#pragma unroll 8
        for (int k = 0; k < 48; k++) {
            float4 wv = wrow[k];
            float4 p  = pv[k];
            acc += wv.x * p.x + wv.y * p.y + wv.z * p.z + wv.w * p.w;
        }
        // partners are lanes (4j..4j+3) within one warp
        acc += __shfl_xor_sync(0xffffffffu, acc, 1);
        acc += __shfl_xor_sync(0xffffffffu, acc, 2);
        if (q == 0) h_s[j] = fmaxf(acc + b1[j], 0.0f);
    }
    __syncthreads();

    // phase 2: s[c] = hardsigmoid(dot(w2[c], h) + b2[c]); c = t
    {
        const float4* hv    = reinterpret_cast<const float4*>(h_s);
        const float4* w2row = w2 + (size_t)t * (HID / 4);
        float a = 0.0f;
#pragma unroll 8
        for (int k = 0; k < HID / 4; k++) {
            float4 wv = w2row[k];
            float4 h  = hv[k];
            a += wv.x * h.x + wv.y * h.y + wv.z * h.z + wv.w * h.w;
        }
        float z = a + b2[t];
        g_scale[b * CH + t] = __saturatef(fmaf(z, 1.0f / 6.0f, 0.5f));
    }
}

// ---------------------------------------------------------------------------
// Kernel 3: out = x * s[plane]. Warp per plane, planes in REVERSE order
// (pool left x's tail in L2). Streaming stores (__stcs) keep the output
// from evicting x's cached lines, so reads stay on the L2 path.
// ---------------------------------------------------------------------------
__global__ __launch_bounds__(256) void scale_kernel(const float4* __restrict__ x,
                                                    float4* __restrict__ out) {
    int w    = (blockIdx.x * blockDim.x + threadIdx.x) >> 5;
    int lane = threadIdx.x & 31;
    if (w >= PLANES) return;

    int plane = PLANES - 1 - w;
    float sv = g_scale[plane];

    const float4* p = x   + (size_t)plane * VEC4;
    float4*       o = out + (size_t)plane * VEC4;

    float4 v[6];
#pragma unroll
    for (int i = 0; i < 6; i++) v[i] = p[lane + 32 * i];
    float4 vt;
    bool tail = lane < 4;
    if (tail) vt = p[192 + lane];

#pragma unroll
    for (int i = 0; i < 6; i++) {
        v[i].x *= sv; v[i].y *= sv; v[i].z *= sv; v[i].w *= sv;
        __stcs(&o[lane + 32 * i], v[i]);
    }
    if (tail) {
        vt.x *= sv; vt.y *= sv; vt.z *= sv; vt.w *= sv;
        __stcs(&o[192 + lane], vt);
    }
}

// ---------------------------------------------------------------------------
extern "C" void kernel_launch(void* const* d_in, const int* in_sizes, int n_in,
                              void* d_out, int out_size) {
    const float4* x  = (const float4*)d_in[0];
    const float4* w1 = (const float4*)d_in[1];
    const float*  b1 = (const float*)d_in[2];
    const float4* w2 = (const float4*)d_in[3];
    const float*  b2 = (const float*)d_in[4];
    float4* out = (float4*)d_out;

    const int warps_per_block = 256 / 32;
    const int grid = (PLANES + warps_per_block - 1) / warps_per_block;  // 6144

    pool_kernel<<<grid, 256>>>(x);
    mlp_kernel<<<BATCH, CH>>>(w1, b1, w2, b2);
    scale_kernel<<<grid, 256>>>(x, out);
}

// round 7
// speedup vs baseline: 1.3491x; 1.2875x over previous
#include <cuda_runtime.h>

// HSE (hard-sigmoid squeeze-excitation) for x[64, 768, 28, 28] fp32.
// R5 vs R4 (115.8us): mlp loads were uncoalesced (32 wavefronts/LDG, ~40us).
// Rebuilt as two warp-per-row kernels with lane-strided coalesced access.
// Pool: 2 planes/warp for deeper MLP. Scale unchanged (at ceiling).

#define BATCH   64
#define CH      768
#define HID     192
#define HW      784
#define PLANES  (BATCH * CH)   // 49152
#define VEC4    (HW / 4)       // 196 float4 per plane

__device__ float g_pooled[PLANES];
__device__ float g_h[BATCH * HID];
__device__ float g_scale[PLANES];

// ---------------------------------------------------------------------------
// Kernel 1: global average pool. Warp per TWO planes (12 loads in flight).
// ---------------------------------------------------------------------------
__global__ __launch_bounds__(256) void pool_kernel(const float4* __restrict__ x) {
    int w    = (blockIdx.x * blockDim.x + threadIdx.x) >> 5;
    int lane = threadIdx.x & 31;
    if (w >= PLANES / 2) return;

    const float4* p0 = x + (size_t)(2 * w) * VEC4;
    const float4* p1 = p0 + VEC4;
    float s0 = 0.0f, s1 = 0.0f;
#pragma unroll
    for (int i = 0; i < 6; i++) {
        float4 a = p0[lane + 32 * i];
        float4 b = p1[lane + 32 * i];
        s0 += (a.x + a.y) + (a.z + a.w);
        s1 += (b.x + b.y) + (b.z + b.w);
    }
    if (lane < 4) {
        float4 a = p0[192 + lane];
        float4 b = p1[192 + lane];
        s0 += (a.x + a.y) + (a.z + a.w);
        s1 += (b.x + b.y) + (b.z + b.w);
    }
#pragma unroll
    for (int off = 16; off; off >>= 1) {
        s0 += __shfl_xor_sync(0xffffffffu, s0, off);
        s1 += __shfl_xor_sync(0xffffffffu, s1, off);
    }
    if (lane == 0) {
        g_pooled[2 * w]     = s0 * (1.0f / 784.0f);
        g_pooled[2 * w + 1] = s1 * (1.0f / 784.0f);
    }
}

// ---------------------------------------------------------------------------
// Kernel 2a: h = relu(w1 @ pooled + b1). Block per batch, 256 threads.
// Warp per row, lanes stride the 768-dot (coalesced float4), shfl reduce.
// ---------------------------------------------------------------------------
__global__ __launch_bounds__(256) void mlp1_kernel(const float4* __restrict__ w1,
                                                   const float*  __restrict__ b1) {
    __shared__ __align__(16) float p_s[CH];
    int b    = blockIdx.x;
    int t    = threadIdx.x;
    int wid  = t >> 5;       // 0..7
    int lane = t & 31;

    p_s[t] = g_pooled[b * CH + t];
    p_s[t + 256] = g_pooled[b * CH + t + 256];
    p_s[t + 512] = g_pooled[b * CH + t + 512];
    __syncthreads();

    const float4* pv = reinterpret_cast<const float4*>(p_s);
#pragma unroll 2
    for (int r = wid; r < HID; r += 8) {
        const float4* wrow = w1 + (size_t)r * (CH / 4);
        float acc = 0.0f;
#pragma unroll
        for (int i = 0; i < 6; i++) {
            float4 wv = wrow[lane + 32 * i];   // coalesced: lanes contiguous
            float4 p  = pv[lane + 32 * i];
            acc += wv.x * p.x + wv.y * p.y + wv.z * p.z + wv.w * p.w;
        }
#pragma unroll
        for (int off = 16; off; off >>= 1)
            acc += __shfl_xor_sync(0xffffffffu, acc, off);
        if (lane == 0) g_h[b * HID + r] = fmaxf(acc + b1[r], 0.0f);
    }
}

// ---------------------------------------------------------------------------
// Kernel 2b: s = hardsigmoid(w2 @ h + b2). Warp per (b,c) output.
// Lanes stride the 192-dot with float2 (coalesced), shfl reduce.
// Grid covers 49152 outputs = 6144 blocks x 8 warps.
// ---------------------------------------------------------------------------
__global__ __launch_bounds__(256) void mlp2_kernel(const float2* __restrict__ w2,
                                                   const float*  __restrict__ b2) {
    int W    = (blockIdx.x * blockDim.x + threadIdx.x) >> 5;
    int lane = threadIdx.x & 31;
    if (W >= PLANES) return;
    int b = W / CH;
    int c = W - b * CH;

    const float2* wrow = w2 + (size_t)c * (HID / 2);
    const float2* hv   = reinterpret_cast<const float2*>(g_h) + b * (HID / 2);
    float acc = 0.0f;
#pragma unroll
    for (int i = 0; i < 3; i++) {
        float2 wv = wrow[lane + 32 * i];       // coalesced 256B
        float2 h  = hv[lane + 32 * i];
        acc += wv.x * h.x + wv.y * h.y;
    }
#pragma unroll
    for (int off = 16; off; off >>= 1)
        acc += __shfl_xor_sync(0xffffffffu, acc, off);
    if (lane == 0) {
        float z = acc + b2[c];
        g_scale[b * CH + c] = __saturatef(fmaf(z, 1.0f / 6.0f, 0.5f));
    }
}

// ---------------------------------------------------------------------------
// Kernel 3: out = x * s[plane]. Warp per plane, reverse order, streaming
// stores. Measured at combined read+write ceiling — unchanged.
// ---------------------------------------------------------------------------
__global__ __launch_bounds__(256) void scale_kernel(const float4* __restrict__ x,
                                                    float4* __restrict__ out) {
    int w    = (blockIdx.x * blockDim.x + threadIdx.x) >> 5;
    int lane = threadIdx.x & 31;
    if (w >= PLANES) return;

    int plane = PLANES - 1 - w;
    float sv = g_scale[plane];

    const float4* p = x   + (size_t)plane * VEC4;
    float4*       o = out + (size_t)plane * VEC4;

    float4 v[6];
#pragma unroll
    for (int i = 0; i < 6; i++) v[i] = p[lane + 32 * i];
    float4 vt;
    bool tail = lane < 4;
    if (tail) vt = p[192 + lane];

#pragma unroll
    for (int i = 0; i < 6; i++) {
        v[i].x *= sv; v[i].y *= sv; v[i].z *= sv; v[i].w *= sv;
        __stcs(&o[lane + 32 * i], v[i]);
    }
    if (tail) {
        vt.x *= sv; vt.y *= sv; vt.z *= sv; vt.w *= sv;
        __stcs(&o[192 + lane], vt);
    }
}

// ---------------------------------------------------------------------------
extern "C" void kernel_launch(void* const* d_in, const int* in_sizes, int n_in,
                              void* d_out, int out_size) {
    const float4* x  = (const float4*)d_in[0];
    const float4* w1 = (const float4*)d_in[1];
    const float*  b1 = (const float*)d_in[2];
    const float2* w2 = (const float2*)d_in[3];
    const float*  b2 = (const float*)d_in[4];
    float4* out = (float4*)d_out;

    pool_kernel<<<PLANES / 2 / 8, 256>>>(x);            // 3072 blocks
    mlp1_kernel<<<BATCH, 256>>>(w1, b1);                // 64 blocks
    mlp2_kernel<<<PLANES / 8, 256>>>(w2, b2);           // 6144 blocks
    scale_kernel<<<PLANES / 8, 256>>>(x, out);          // 6144 blocks
}